// round 16
// baseline (speedup 1.0000x reference)
#include <cuda_runtime.h>
#include <cuda_bf16.h>
#include <cstdint>

// ---------------- problem constants ----------------
#define MROWS 8192          // 2*N rows
#define HID   256
#define K1    1024          // expanded K: [x_hi, x_hi, x_lo, x^3]
#define KW    768           // hi/lo split K for C prep
#define NCOORD (4096 * 6)

#define TILE_M 64
#define TILE_N 256          // full width per CTA (grid.y used only by prep N=512)
#define KC     64                   // K chunk: 64 bf16 = 128B rows
// warp-private staging: A 32 rows (4KB) + B 64 rows (8KB) per stage
#define WARP_A_BYTES 4096
#define WARP_STAGE   12288          // A 4KB + B 8KB
#define NSTAGE 2
#define WARP_SMEM (NSTAGE * WARP_STAGE)     // 24576 per warp
#define SMEM_TOTAL (8 * WARP_SMEM)          // 196608 (192KB)

// ---------------- device scratch (allocation-free) ----------------
__device__ __align__(256) __nv_bfloat16 g_XA[(size_t)MROWS * K1];     // ping
__device__ __align__(256) __nv_bfloat16 g_XB[(size_t)MROWS * K1];     // pong
__device__ __align__(256) __nv_bfloat16 g_Wexp[(size_t)5 * HID * K1]; // merged weights l=0..3 + w_last l=4
__device__ __align__(256) __nv_bfloat16 g_Ap[(size_t)4 * HID * KW];   // W1 split [hi,hi,lo]
__device__ __align__(256) __nv_bfloat16 g_Bp[(size_t)4 * 512 * KW];   // rows 0-255: WsinT split [hi,lo,hi]; 256-511: [WsinT^3/6,0,0]

// ---------------- helpers ----------------
__device__ __forceinline__ uint32_t smem_u32(const void* p) {
    uint32_t a;
    asm("{ .reg .u64 t; cvta.to.shared.u64 t, %1; cvt.u32.u64 %0, t; }" : "=r"(a) : "l"(p));
    return a;
}
__device__ __forceinline__ uint32_t bf2u(float a, float b) {
    __nv_bfloat162 t = __floats2bfloat162_rn(a, b);
    return *reinterpret_cast<uint32_t*>(&t);
}

// ---------------- prep kernels ----------------
// y<4: w1[y] -> Ap[y] = split [hi,hi,lo] (K=768)
// y==4: w_last -> Wexp[4] slots [w_hi, w_lo, w_hi, -w^3/6] (K1 layout)
__global__ void prep_w_kernel(const float* __restrict__ w1, const float* __restrict__ w_last,
                              __nv_bfloat16* __restrict__ Ap, __nv_bfloat16* __restrict__ WexpLast) {
    int l = blockIdx.y;
    int idx = blockIdx.x * 256 + threadIdx.x;       // 0..65535
    if (l < 4) {
        float w = w1[(size_t)l * 65536 + idx];
        int j = idx >> 8, h = idx & 255;
        float hi = __bfloat162float(__float2bfloat16_rn(w));
        float lo = w - hi;
        __nv_bfloat16* o = Ap + (size_t)l * HID * KW + (size_t)j * KW + h;
        o[0]   = __float2bfloat16_rn(hi);
        o[256] = __float2bfloat16_rn(hi);
        o[512] = __float2bfloat16_rn(lo);
    } else {
        float w = w_last[idx];
        int h = idx >> 8, k = idx & 255;
        __nv_bfloat16* o = WexpLast + (size_t)h * K1 + k;
        float hi = __bfloat162float(__float2bfloat16_rn(w));
        float lo = w - hi;
        o[0]   = __float2bfloat16_rn(hi);
        o[256] = __float2bfloat16_rn(lo);
        o[512] = __float2bfloat16_rn(hi);
        o[768] = __float2bfloat16_rn(-w * w * w * (1.0f / 6.0f));
    }
}

// Wsin_l transposed -> Bp[l] rows 0-255 = split [hi,lo,hi]; rows 256-511 = [w^3/6, 0, 0]
__global__ void prep_wsinT_kernel(const float* __restrict__ w0, const float* __restrict__ ws,
                                  __nv_bfloat16* __restrict__ Bp) {
    __shared__ float t[32][33];
    int l = blockIdx.z;
    const float* src = (l == 0) ? w0 : ws + (size_t)(l - 1) * 65536;
    int h0 = blockIdx.y * 32, kk0 = blockIdx.x * 32;
    int x = threadIdx.x, y = threadIdx.y;          // 32 x 8
#pragma unroll
    for (int i = 0; i < 4; i++)
        t[y + i * 8][x] = src[(size_t)(h0 + y + i * 8) * 256 + kk0 + x];
    __syncthreads();
#pragma unroll
    for (int i = 0; i < 4; i++) {
        int kkoff = y + i * 8;
        float w = t[x][kkoff];                     // = Wsin[h0+x][kk0+kkoff]
        float hi = __bfloat162float(__float2bfloat16_rn(w));
        float lo = w - hi;
        __nv_bfloat16* o = Bp + (size_t)l * 512 * KW + (size_t)(kk0 + kkoff) * KW + h0 + x;
        o[0]   = __float2bfloat16_rn(hi);
        o[256] = __float2bfloat16_rn(lo);
        o[512] = __float2bfloat16_rn(hi);
        __nv_bfloat16* o2 = Bp + (size_t)l * 512 * KW + (size_t)(256 + kk0 + kkoff) * KW + h0 + x;
        o2[0]   = __float2bfloat16_rn(w * w * w * (1.0f / 6.0f));
        o2[256] = __float2bfloat16_rn(0.f);
        o2[512] = __float2bfloat16_rn(0.f);
    }
}

// ---------------- Fourier features -> expanded activations ----------------
__device__ __forceinline__ void write4(__nv_bfloat16* r, int j, float v) {
    float hi = __bfloat162float(__float2bfloat16_rn(v));
    float lo = v - hi;
    r[j]       = __float2bfloat16_rn(hi);
    r[256 + j] = __float2bfloat16_rn(hi);
    r[512 + j] = __float2bfloat16_rn(lo);
    r[768 + j] = __float2bfloat16_rn(v * v * v);
}
__global__ void fourier_kernel(const float* __restrict__ coords, const float* __restrict__ B,
                               __nv_bfloat16* __restrict__ X) {
    int m = blockIdx.x;       // 0..8191
    int f = threadIdx.x;      // 0..127
    float x0, x1, x2;
    if (m < 4096) {
        const float* c = coords + m * 6;
        x0 = c[0]; x1 = c[1]; x2 = c[2];
    } else {
        const float* c = coords + (m - 4096) * 6;
        x0 = c[3]; x1 = c[4]; x2 = c[5];
    }
    float p = x0 * __ldg(&B[f]) + x1 * __ldg(&B[128 + f]) + x2 * __ldg(&B[256 + f]);
    p *= 6.283185307179586f;
    __nv_bfloat16* r = X + (size_t)m * K1;
    write4(r, f, sinf(p));
    write4(r, 128 + f, cosf(p));
}

// ---------------- barrier-free warp-self-paced HMMA GEMM ----------------
// D[m,n] = sum_k A[m,k]*B[n,k]  (both K-major), fp32 accum.
// CTA tile 64x256, 8 warps (warp tile 32x64). Each warp cp.asyncs its OWN
// A-rows and B-rows into warp-private smem (2 stages), so cp.async.wait_group
// (per-thread) is sufficient: ZERO __syncthreads in the mainloop — warps
// free-run and self-pace. Fragment double-buffering across ks steps.
// EPI 1: y = sin(D + bias[n]) -> 4-slot expansion (K1 layout)
// EPI 2: fp32 D -> out (HID row stride)
// EPI 6: merged prep: cols 0-255 -> hi/lo split of C1 into Wexp[z] slots 0..2;
//        cols 256-511 -> -C3 into Wexp[z] slot 3 (offset 768). Row stride K1.
template <int KTOT, int EPI>
__global__ __launch_bounds__(256, 1)
void gemm_kernel(const __nv_bfloat16* __restrict__ A, const __nv_bfloat16* __restrict__ Bw,
                 const float* __restrict__ bias, void* __restrict__ outp,
                 size_t aBatch, size_t bBatch) {
    extern __shared__ char smem[];
    const int tid = threadIdx.x;
    const int lane = tid & 31;
    const int wid = tid >> 5;       // 0..7
    const int warp_m = wid & 1;     // 0..1 : 32-row slab
    const int warp_n = wid >> 1;    // 0..3 : 64-col slab
    const int m0 = blockIdx.x * TILE_M;
    const int n0 = blockIdx.y * TILE_N;
    A  += (size_t)blockIdx.z * aBatch;
    Bw += (size_t)blockIdx.z * bBatch;

    const uint32_t wbase = smem_u32(smem) + (uint32_t)wid * WARP_SMEM;

    float acc[2][8][4];
#pragma unroll
    for (int i = 0; i < 2; i++)
#pragma unroll
        for (int j = 0; j < 8; j++)
#pragma unroll
            for (int e = 0; e < 4; e++) acc[i][j][e] = 0.f;

    constexpr int NCH = KTOT / KC;
    static_assert(NCH >= 2, "pipeline needs >= 2 chunks");

    // ---- warp-private stage loader: this warp's A rows (32) + B rows (64) ----
    auto issue_loads = [&](int c) {
        const int k0 = c * KC;
        const uint32_t stA = wbase + (uint32_t)(c & 1) * WARP_STAGE;
        const uint32_t stB = stA + WARP_A_BYTES;
        // A: 32 rows x 8 segs = 256 units, 8 per lane
#pragma unroll
        for (int i = 0; i < 8; i++) {
            int u = lane + i * 32;
            int r = u >> 3, s8 = u & 7;
            uint32_t off = (uint32_t)(r * 128 + ((s8 ^ (r & 7)) << 4));
            const void* src = A + (size_t)(m0 + warp_m * 32 + r) * KTOT + k0 + s8 * 8;
            asm volatile("cp.async.cg.shared.global [%0], [%1], 16;"
                         :: "r"(stA + off), "l"(src));
        }
        // B: 64 rows x 8 segs = 512 units, 16 per lane
#pragma unroll
        for (int i = 0; i < 16; i++) {
            int u = lane + i * 32;
            int r = u >> 3, s8 = u & 7;
            uint32_t off = (uint32_t)(r * 128 + ((s8 ^ (r & 7)) << 4));
            const void* src = Bw + (size_t)(n0 + warp_n * 64 + r) * KTOT + k0 + s8 * 8;
            asm volatile("cp.async.cg.shared.global [%0], [%1], 16;"
                         :: "r"(stB + off), "l"(src));
        }
    };

    // fragment loader for one ks step (K=16 slice): A 2 frags, B 4 frags (warp-local rows)
    auto load_frags = [&](uint32_t stA, uint32_t stB, int ks,
                          uint32_t (*af)[4], uint32_t (*bfr)[4]) {
#pragma unroll
        for (int mi = 0; mi < 2; mi++) {
            int row = mi * 16 + (lane & 15);               // local 0..31
            int seg = ks * 2 + (lane >> 4);
            uint32_t ad = stA + (uint32_t)(row * 128 + ((seg ^ (row & 7)) << 4));
            asm volatile("ldmatrix.sync.aligned.m8n8.x4.shared.b16 {%0,%1,%2,%3}, [%4];"
                         : "=r"(af[mi][0]), "=r"(af[mi][1]), "=r"(af[mi][2]), "=r"(af[mi][3])
                         : "r"(ad));
        }
#pragma unroll
        for (int bi = 0; bi < 4; bi++) {
            int nrow = bi * 16 + (lane & 7) + ((lane >> 4) << 3);  // local 0..63
            int seg = ks * 2 + ((lane >> 3) & 1);
            uint32_t ad = stB + (uint32_t)(nrow * 128 + ((seg ^ (nrow & 7)) << 4));
            asm volatile("ldmatrix.sync.aligned.m8n8.x4.shared.b16 {%0,%1,%2,%3}, [%4];"
                         : "=r"(bfr[bi][0]), "=r"(bfr[bi][1]), "=r"(bfr[bi][2]), "=r"(bfr[bi][3])
                         : "r"(ad));
        }
    };

    issue_loads(0); asm volatile("cp.async.commit_group;");
    issue_loads(1); asm volatile("cp.async.commit_group;");

    for (int c = 0; c < NCH; c++) {
        asm volatile("cp.async.wait_group 1;");   // this warp's chunk c complete
        const uint32_t stA = wbase + (uint32_t)(c & 1) * WARP_STAGE;
        const uint32_t stB = stA + WARP_A_BYTES;

        uint32_t af[2][2][4], bf[2][4][4];        // double-buffered fragments
        load_frags(stA, stB, 0, af[0], bf[0]);
#pragma unroll
        for (int ks = 0; ks < 4; ks++) {
            if (ks < 3) load_frags(stA, stB, ks + 1, af[(ks + 1) & 1], bf[(ks + 1) & 1]);
            uint32_t (*a)[4] = af[ks & 1];
            uint32_t (*b)[4] = bf[ks & 1];
#pragma unroll
            for (int mi = 0; mi < 2; mi++)
#pragma unroll
                for (int ni = 0; ni < 8; ni++) {
                    uint32_t b0 = b[ni >> 1][(ni & 1) * 2];
                    uint32_t b1 = b[ni >> 1][(ni & 1) * 2 + 1];
                    asm volatile(
                        "mma.sync.aligned.m16n8k16.row.col.f32.bf16.bf16.f32 "
                        "{%0,%1,%2,%3}, {%4,%5,%6,%7}, {%8,%9}, {%0,%1,%2,%3};"
                        : "+f"(acc[mi][ni][0]), "+f"(acc[mi][ni][1]),
                          "+f"(acc[mi][ni][2]), "+f"(acc[mi][ni][3])
                        : "r"(a[mi][0]), "r"(a[mi][1]), "r"(a[mi][2]), "r"(a[mi][3]),
                          "r"(b0), "r"(b1));
                }
        }
        // all LDSM of slot c&1 done (ldmatrix is sync) -> safe to overwrite
        if (c + 2 < NCH) issue_loads(c + 2);
        asm volatile("cp.async.commit_group;");
    }

    // ---- epilogue (warp-local, no sync needed) ----
    const int q = lane >> 2;
    const int tq = lane & 3;
#pragma unroll
    for (int mi = 0; mi < 2; mi++) {
#pragma unroll
        for (int h = 0; h < 2; h++) {
            const int m = m0 + warp_m * 32 + mi * 16 + h * 8 + q;
#pragma unroll
            for (int ni = 0; ni < 8; ni++) {
                const int col = n0 + warp_n * 64 + ni * 8 + tq * 2;
                float v0 = acc[mi][ni][h * 2 + 0];
                float v1 = acc[mi][ni][h * 2 + 1];
                if (EPI == 1) {
                    __nv_bfloat16* d0 = (__nv_bfloat16*)outp + (size_t)m * K1 + col;
                    float z0 = v0 + __ldg(bias + col);
                    float z1 = v1 + __ldg(bias + col + 1);
                    float y0 = sinf(z0), y1 = sinf(z1);
                    float h0 = __bfloat162float(__float2bfloat16_rn(y0));
                    float h1 = __bfloat162float(__float2bfloat16_rn(y1));
                    uint32_t uh = bf2u(h0, h1);
                    *(uint32_t*)(d0)       = uh;
                    *(uint32_t*)(d0 + 256) = uh;
                    *(uint32_t*)(d0 + 512) = bf2u(y0 - h0, y1 - h1);
                    *(uint32_t*)(d0 + 768) = bf2u(y0 * y0 * y0, y1 * y1 * y1);
                } else if (EPI == 2) {
                    float* O = (float*)outp + (size_t)m * HID + col;
                    *reinterpret_cast<float2*>(O) = make_float2(v0, v1);
                } else {  // EPI == 6: merged prep (N-concat over grid.y)
                    __nv_bfloat16* base = (__nv_bfloat16*)outp + (size_t)blockIdx.z * HID * K1
                                          + (size_t)m * K1;
                    if (col < 256) {
                        __nv_bfloat16* d0 = base + col;
                        float h0 = __bfloat162float(__float2bfloat16_rn(v0));
                        float h1 = __bfloat162float(__float2bfloat16_rn(v1));
                        uint32_t uh = bf2u(h0, h1);
                        *(uint32_t*)(d0)       = uh;
                        *(uint32_t*)(d0 + 256) = bf2u(v0 - h0, v1 - h1);
                        *(uint32_t*)(d0 + 512) = uh;
                    } else {
                        __nv_bfloat16* d0 = base + 768 + (col - 256);
                        *(uint32_t*)(d0) = bf2u(-v0, -v1);
                    }
                }
            }
        }
    }
}

// coords passthrough (tuple element #2)
__global__ void copy_kernel(const float* __restrict__ src, float* __restrict__ dst, int n) {
    int i = blockIdx.x * blockDim.x + threadIdx.x;
    if (i < n) dst[i] = src[i];
}

extern "C" void kernel_launch(void* const* d_in, const int* in_sizes, int n_in,
                              void* d_out, int out_size) {
    const float* coords = (const float*)d_in[0];  // (4096, 6)
    const float* B      = (const float*)d_in[1];  // (3, 128)
    const float* w0     = (const float*)d_in[2];  // (256, 256)
    const float* ws     = (const float*)d_in[3];  // (3, 256, 256)
    const float* w_last = (const float*)d_in[4];  // (256, 256)
    const float* w1     = (const float*)d_in[5];  // (4, 256, 256)
    const float* b1     = (const float*)d_in[6];  // (4, 256)
    float* out = (float*)d_out;

    __nv_bfloat16 *XA, *XB, *Wexp, *Ap, *Bp;
    cudaGetSymbolAddress((void**)&XA, g_XA);
    cudaGetSymbolAddress((void**)&XB, g_XB);
    cudaGetSymbolAddress((void**)&Wexp, g_Wexp);
    cudaGetSymbolAddress((void**)&Ap, g_Ap);
    cudaGetSymbolAddress((void**)&Bp, g_Bp);

    cudaFuncSetAttribute(gemm_kernel<K1, 1>, cudaFuncAttributeMaxDynamicSharedMemorySize, SMEM_TOTAL);
    cudaFuncSetAttribute(gemm_kernel<K1, 2>, cudaFuncAttributeMaxDynamicSharedMemorySize, SMEM_TOTAL);
    cudaFuncSetAttribute(gemm_kernel<KW, 6>, cudaFuncAttributeMaxDynamicSharedMemorySize, SMEM_TOTAL);

    // ---- fork a side stream for the weight-prep chain (graph branch) ----
    cudaStream_t side = nullptr;
    cudaEvent_t evFork = nullptr, evJoin = nullptr;
    bool fork_ok =
        (cudaStreamCreateWithFlags(&side, cudaStreamNonBlocking) == cudaSuccess) &&
        (cudaEventCreateWithFlags(&evFork, cudaEventDisableTiming) == cudaSuccess) &&
        (cudaEventCreateWithFlags(&evJoin, cudaEventDisableTiming) == cudaSuccess);
    if (fork_ok) fork_ok = (cudaEventRecord(evFork, 0) == cudaSuccess) &&
                           (cudaStreamWaitEvent(side, evFork, 0) == cudaSuccess);
    cudaStream_t prepS = fork_ok ? side : (cudaStream_t)0;

    // ---- weight prep chain (side stream when forked) ----
    prep_w_kernel<<<dim3(256, 5), 256, 0, prepS>>>(w1, w_last, Ap, Wexp + (size_t)4 * HID * K1);
    prep_wsinT_kernel<<<dim3(8, 8, 4), dim3(32, 8), 0, prepS>>>(w0, ws, Bp);
    // Single merged prep GEMM: N=512 via grid.y (cols 0-255 -> C1 split, 256-511 -> -C3)
    gemm_kernel<KW, 6><<<dim3(4, 2, 4), 256, SMEM_TOTAL, prepS>>>(
        Ap, Bp, nullptr, Wexp, (size_t)HID * KW, (size_t)512 * KW);

    // ---- activation chain (main stream, concurrent with prep) ----
    fourier_kernel<<<MROWS, 128>>>(coords, B, XA);
    copy_kernel<<<(NCOORD + 255) / 256, 256>>>(coords, out + (size_t)MROWS * HID, NCOORD);

    // ---- join ----
    if (fork_ok) {
        cudaEventRecord(evJoin, side);
        cudaStreamWaitEvent(0, evJoin, 0);
    }

    // ---- network ----
    const dim3 grid(MROWS / TILE_M, 1, 1);  // (128, 1) = 128 CTAs, 1/SM
    __nv_bfloat16* bufs[2] = { XA, XB };
    for (int l = 0; l < 4; l++) {
        gemm_kernel<K1, 1><<<grid, 256, SMEM_TOTAL>>>(
            bufs[l & 1], Wexp + (size_t)l * HID * K1, b1 + l * 256, bufs[(l + 1) & 1], 0, 0);
    }
    gemm_kernel<K1, 2><<<grid, 256, SMEM_TOTAL>>>(
        XA, Wexp + (size_t)4 * HID * K1, nullptr, out, 0, 0);
    // (stream/event objects intentionally not destroyed: host-side only, few calls)
}

// round 17
// speedup vs baseline: 1.0870x; 1.0870x over previous
#include <cuda_runtime.h>
#include <cuda_bf16.h>
#include <cstdint>

// ---------------- problem constants ----------------
#define MROWS 8192          // 2*N rows
#define HID   256
#define K1    1024          // expanded K: [x_hi, x_hi, x_lo, x^3]
#define KW    768           // hi/lo split K for C prep
#define NCOORD (4096 * 6)

#define TILE_M 64
#define TILE_N 128
#define KC     64                  // K chunk: 64 bf16 = 128B rows
#define STAGE_A  8192               // 64 rows * 128B
#define STAGE_BYTES 24576           // A 8KB + B 16KB
#define NSTAGE 4
#define SMEM_TOTAL (NSTAGE * STAGE_BYTES)   // 98304

// ---------------- device scratch (allocation-free) ----------------
__device__ __align__(256) __nv_bfloat16 g_XA[(size_t)MROWS * K1];     // ping
__device__ __align__(256) __nv_bfloat16 g_XB[(size_t)MROWS * K1];     // pong
__device__ __align__(256) __nv_bfloat16 g_Wexp[(size_t)5 * HID * K1]; // merged weights l=0..3 + w_last l=4
__device__ __align__(256) __nv_bfloat16 g_Ap[(size_t)4 * HID * KW];   // W1 split [hi,hi,lo]
__device__ __align__(256) __nv_bfloat16 g_Bp[(size_t)4 * 512 * KW];   // rows 0-255: WsinT split [hi,lo,hi]; 256-511: [WsinT^3/6,0,0]

// ---------------- helpers ----------------
__device__ __forceinline__ uint32_t smem_u32(const void* p) {
    uint32_t a;
    asm("{ .reg .u64 t; cvta.to.shared.u64 t, %1; cvt.u32.u64 %0, t; }" : "=r"(a) : "l"(p));
    return a;
}
__device__ __forceinline__ uint32_t bf2u(float a, float b) {
    __nv_bfloat162 t = __floats2bfloat162_rn(a, b);
    return *reinterpret_cast<uint32_t*>(&t);
}

// ---------------- prep kernels ----------------
// y<4: w1[y] -> Ap[y] = split [hi,hi,lo] (K=768)
// y==4: w_last -> Wexp[4] slots [w_hi, w_lo, w_hi, -w^3/6] (K1 layout)
__global__ void prep_w_kernel(const float* __restrict__ w1, const float* __restrict__ w_last,
                              __nv_bfloat16* __restrict__ Ap, __nv_bfloat16* __restrict__ WexpLast) {
    int l = blockIdx.y;
    int idx = blockIdx.x * 256 + threadIdx.x;       // 0..65535
    if (l < 4) {
        float w = w1[(size_t)l * 65536 + idx];
        int j = idx >> 8, h = idx & 255;
        float hi = __bfloat162float(__float2bfloat16_rn(w));
        float lo = w - hi;
        __nv_bfloat16* o = Ap + (size_t)l * HID * KW + (size_t)j * KW + h;
        o[0]   = __float2bfloat16_rn(hi);
        o[256] = __float2bfloat16_rn(hi);
        o[512] = __float2bfloat16_rn(lo);
    } else {
        float w = w_last[idx];
        int h = idx >> 8, k = idx & 255;
        __nv_bfloat16* o = WexpLast + (size_t)h * K1 + k;
        float hi = __bfloat162float(__float2bfloat16_rn(w));
        float lo = w - hi;
        o[0]   = __float2bfloat16_rn(hi);
        o[256] = __float2bfloat16_rn(lo);
        o[512] = __float2bfloat16_rn(hi);
        o[768] = __float2bfloat16_rn(-w * w * w * (1.0f / 6.0f));
    }
}

// Wsin_l transposed -> Bp[l] rows 0-255 = split [hi,lo,hi]; rows 256-511 = [w^3/6, 0, 0]
__global__ void prep_wsinT_kernel(const float* __restrict__ w0, const float* __restrict__ ws,
                                  __nv_bfloat16* __restrict__ Bp) {
    __shared__ float t[32][33];
    int l = blockIdx.z;
    const float* src = (l == 0) ? w0 : ws + (size_t)(l - 1) * 65536;
    int h0 = blockIdx.y * 32, kk0 = blockIdx.x * 32;
    int x = threadIdx.x, y = threadIdx.y;          // 32 x 8
#pragma unroll
    for (int i = 0; i < 4; i++)
        t[y + i * 8][x] = src[(size_t)(h0 + y + i * 8) * 256 + kk0 + x];
    __syncthreads();
#pragma unroll
    for (int i = 0; i < 4; i++) {
        int kkoff = y + i * 8;
        float w = t[x][kkoff];                     // = Wsin[h0+x][kk0+kkoff]
        float hi = __bfloat162float(__float2bfloat16_rn(w));
        float lo = w - hi;
        __nv_bfloat16* o = Bp + (size_t)l * 512 * KW + (size_t)(kk0 + kkoff) * KW + h0 + x;
        o[0]   = __float2bfloat16_rn(hi);
        o[256] = __float2bfloat16_rn(lo);
        o[512] = __float2bfloat16_rn(hi);
        __nv_bfloat16* o2 = Bp + (size_t)l * 512 * KW + (size_t)(256 + kk0 + kkoff) * KW + h0 + x;
        o2[0]   = __float2bfloat16_rn(w * w * w * (1.0f / 6.0f));
        o2[256] = __float2bfloat16_rn(0.f);
        o2[512] = __float2bfloat16_rn(0.f);
    }
}

// ---------------- Fourier features -> expanded activations ----------------
__device__ __forceinline__ void write4(__nv_bfloat16* r, int j, float v) {
    float hi = __bfloat162float(__float2bfloat16_rn(v));
    float lo = v - hi;
    r[j]       = __float2bfloat16_rn(hi);
    r[256 + j] = __float2bfloat16_rn(hi);
    r[512 + j] = __float2bfloat16_rn(lo);
    r[768 + j] = __float2bfloat16_rn(v * v * v);
}
__global__ void fourier_kernel(const float* __restrict__ coords, const float* __restrict__ B,
                               __nv_bfloat16* __restrict__ X) {
    int m = blockIdx.x;       // 0..8191
    int f = threadIdx.x;      // 0..127
    float x0, x1, x2;
    if (m < 4096) {
        const float* c = coords + m * 6;
        x0 = c[0]; x1 = c[1]; x2 = c[2];
    } else {
        const float* c = coords + (m - 4096) * 6;
        x0 = c[3]; x1 = c[4]; x2 = c[5];
    }
    float p = x0 * __ldg(&B[f]) + x1 * __ldg(&B[128 + f]) + x2 * __ldg(&B[256 + f]);
    p *= 6.283185307179586f;
    __nv_bfloat16* r = X + (size_t)m * K1;
    write4(r, f, sinf(p));
    write4(r, 128 + f, cosf(p));
}

// ---------------- HMMA GEMM with fused epilogue + PDL ----------------
// D[m,n] = sum_k A[m,k]*B[n,k]  (both K-major), fp32 accum.
// CTA tile 64x128, 8 warps (warp 32x32), 4-stage cp.async, depth-2 prefetch,
// software-pipelined ldmatrix fragments. PDL: B (weights) of chunks 0..2 are
// prefetched BEFORE cudaGridDependencySynchronize(); A loads after. Trigger
// fires after the mainloop so the successor launches during epilogue/drain.
// EPI 1: y = sin(D + bias[n]) -> 4-slot expansion (K1 layout)
// EPI 2: fp32 D -> out (HID row stride)
// EPI 6: merged prep: cols 0-255 -> hi/lo split of C1 into Wexp[z] slots 0..2;
//        cols 256-511 -> -C3 into Wexp[z] slot 3 (offset 768). Row stride K1.
template <int KTOT, int EPI>
__global__ __launch_bounds__(256, 2)
void gemm_kernel(const __nv_bfloat16* __restrict__ A, const __nv_bfloat16* __restrict__ Bw,
                 const float* __restrict__ bias, void* __restrict__ outp,
                 size_t aBatch, size_t bBatch) {
    extern __shared__ char smem[];
    const uint32_t sb = smem_u32(smem);
    const int tid = threadIdx.x;
    const int lane = tid & 31;
    const int wid = tid >> 5;
    const int warp_m = wid & 1;     // 0..1 : 32-row slab
    const int warp_n = wid >> 1;    // 0..3 : 32-col slab
    const int m0 = blockIdx.x * TILE_M;
    const int n0 = blockIdx.y * TILE_N;
    A  += (size_t)blockIdx.z * aBatch;
    Bw += (size_t)blockIdx.z * bBatch;

    float acc[2][4][4];
#pragma unroll
    for (int i = 0; i < 2; i++)
#pragma unroll
        for (int j = 0; j < 4; j++)
#pragma unroll
            for (int e = 0; e < 4; e++) acc[i][j][e] = 0.f;

    constexpr int NCH = KTOT / KC;
    static_assert(NCH >= 3, "pipeline needs >= 3 chunks");

    auto issue_loads_A = [&](int c) {
        const int k0 = c * KC;
        const uint32_t dbase = sb + (uint32_t)(c % NSTAGE) * STAGE_BYTES;
#pragma unroll
        for (int i = 0; i < 2; i++) {              // A: 64 rows x 8 segs
            int idx = tid + i * 256;
            int r = idx >> 3, s8 = idx & 7;
            uint32_t off = (uint32_t)(r * 128 + ((s8 ^ (r & 7)) << 4));
            const void* srcA = A + (size_t)(m0 + r) * KTOT + k0 + s8 * 8;
            asm volatile("cp.async.cg.shared.global [%0], [%1], 16;"
                         :: "r"(dbase + off), "l"(srcA));
        }
    };
    auto issue_loads_B = [&](int c) {
        const int k0 = c * KC;
        const uint32_t dbase = sb + (uint32_t)(c % NSTAGE) * STAGE_BYTES;
#pragma unroll
        for (int i = 0; i < 4; i++) {              // B: 128 rows x 8 segs
            int idx = tid + i * 256;
            int r = idx >> 3, s8 = idx & 7;
            uint32_t off = (uint32_t)(r * 128 + ((s8 ^ (r & 7)) << 4));
            const void* srcB = Bw + (size_t)(n0 + r) * KTOT + k0 + s8 * 8;
            asm volatile("cp.async.cg.shared.global [%0], [%1], 16;"
                         :: "r"(dbase + STAGE_A + off), "l"(srcB));
        }
    };

    auto load_frags = [&](uint32_t sA, uint32_t sB, int ks,
                          uint32_t (*af)[4], uint32_t (*bfr)[4]) {
#pragma unroll
        for (int mi = 0; mi < 2; mi++) {
            int row = warp_m * 32 + mi * 16 + (lane & 15);
            int seg = ks * 2 + (lane >> 4);
            uint32_t ad = sA + (uint32_t)(row * 128 + ((seg ^ (row & 7)) << 4));
            asm volatile("ldmatrix.sync.aligned.m8n8.x4.shared.b16 {%0,%1,%2,%3}, [%4];"
                         : "=r"(af[mi][0]), "=r"(af[mi][1]), "=r"(af[mi][2]), "=r"(af[mi][3])
                         : "r"(ad));
        }
#pragma unroll
        for (int bi = 0; bi < 2; bi++) {
            int nrow = warp_n * 32 + bi * 16 + (lane & 7) + ((lane >> 4) << 3);
            int seg = ks * 2 + ((lane >> 3) & 1);
            uint32_t ad = sB + (uint32_t)(nrow * 128 + ((seg ^ (nrow & 7)) << 4));
            asm volatile("ldmatrix.sync.aligned.m8n8.x4.shared.b16 {%0,%1,%2,%3}, [%4];"
                         : "=r"(bfr[bi][0]), "=r"(bfr[bi][1]), "=r"(bfr[bi][2]), "=r"(bfr[bi][3])
                         : "r"(ad));
        }
    };

    // ---- PDL prologue: weight (B) prefetch has no dependency on predecessor ----
    issue_loads_B(0);
    issue_loads_B(1);
    issue_loads_B(2);
    cudaGridDependencySynchronize();               // predecessor output now visible
    issue_loads_A(0); asm volatile("cp.async.commit_group;");  // group0 = {B0,B1,B2,A0}
    issue_loads_A(1); asm volatile("cp.async.commit_group;");  // group1 = {A1}
    issue_loads_A(2); asm volatile("cp.async.commit_group;");  // group2 = {A2}

    for (int c = 0; c < NCH; c++) {
        asm volatile("cp.async.wait_group 2;");   // groups <= c complete
        __syncthreads();
        if (c + 3 < NCH) { issue_loads_A(c + 3); issue_loads_B(c + 3); }
        asm volatile("cp.async.commit_group;");

        const uint32_t sA = sb + (uint32_t)(c % NSTAGE) * STAGE_BYTES;
        const uint32_t sB = sA + STAGE_A;

        uint32_t af[2][2][4], bf[2][2][4];
        load_frags(sA, sB, 0, af[0], bf[0]);
#pragma unroll
        for (int ks = 0; ks < 4; ks++) {
            if (ks < 3) load_frags(sA, sB, ks + 1, af[(ks + 1) & 1], bf[(ks + 1) & 1]);
            uint32_t (*a)[4] = af[ks & 1];
            uint32_t (*b)[4] = bf[ks & 1];
#pragma unroll
            for (int mi = 0; mi < 2; mi++)
#pragma unroll
                for (int ni = 0; ni < 4; ni++) {
                    uint32_t b0 = b[ni >> 1][(ni & 1) * 2];
                    uint32_t b1 = b[ni >> 1][(ni & 1) * 2 + 1];
                    asm volatile(
                        "mma.sync.aligned.m16n8k16.row.col.f32.bf16.bf16.f32 "
                        "{%0,%1,%2,%3}, {%4,%5,%6,%7}, {%8,%9}, {%0,%1,%2,%3};"
                        : "+f"(acc[mi][ni][0]), "+f"(acc[mi][ni][1]),
                          "+f"(acc[mi][ni][2]), "+f"(acc[mi][ni][3])
                        : "r"(a[mi][0]), "r"(a[mi][1]), "r"(a[mi][2]), "r"(a[mi][3]),
                          "r"(b0), "r"(b1));
                }
        }
    }

    // Let the dependent kernel launch while we run the epilogue / drain.
    cudaTriggerProgrammaticLaunchCompletion();

    // ---- epilogue ----
    const int q = lane >> 2;
    const int tq = lane & 3;
#pragma unroll
    for (int mi = 0; mi < 2; mi++) {
#pragma unroll
        for (int h = 0; h < 2; h++) {
            const int m = m0 + warp_m * 32 + mi * 16 + h * 8 + q;
#pragma unroll
            for (int ni = 0; ni < 4; ni++) {
                const int col = n0 + warp_n * 32 + ni * 8 + tq * 2;
                float v0 = acc[mi][ni][h * 2 + 0];
                float v1 = acc[mi][ni][h * 2 + 1];
                if (EPI == 1) {
                    __nv_bfloat16* d0 = (__nv_bfloat16*)outp + (size_t)m * K1 + col;
                    float z0 = v0 + __ldg(bias + col);
                    float z1 = v1 + __ldg(bias + col + 1);
                    float y0 = sinf(z0), y1 = sinf(z1);
                    float h0 = __bfloat162float(__float2bfloat16_rn(y0));
                    float h1 = __bfloat162float(__float2bfloat16_rn(y1));
                    uint32_t uh = bf2u(h0, h1);
                    *(uint32_t*)(d0)       = uh;
                    *(uint32_t*)(d0 + 256) = uh;
                    *(uint32_t*)(d0 + 512) = bf2u(y0 - h0, y1 - h1);
                    *(uint32_t*)(d0 + 768) = bf2u(y0 * y0 * y0, y1 * y1 * y1);
                } else if (EPI == 2) {
                    float* O = (float*)outp + (size_t)m * HID + col;
                    *reinterpret_cast<float2*>(O) = make_float2(v0, v1);
                } else {  // EPI == 6: merged prep (N-concat)
                    __nv_bfloat16* base = (__nv_bfloat16*)outp + (size_t)blockIdx.z * HID * K1
                                          + (size_t)m * K1;
                    if (col < 256) {
                        __nv_bfloat16* d0 = base + col;
                        float h0 = __bfloat162float(__float2bfloat16_rn(v0));
                        float h1 = __bfloat162float(__float2bfloat16_rn(v1));
                        uint32_t uh = bf2u(h0, h1);
                        *(uint32_t*)(d0)       = uh;
                        *(uint32_t*)(d0 + 256) = bf2u(v0 - h0, v1 - h1);
                        *(uint32_t*)(d0 + 512) = uh;
                    } else {
                        __nv_bfloat16* d0 = base + 768 + (col - 256);
                        *(uint32_t*)(d0) = bf2u(-v0, -v1);
                    }
                }
            }
        }
    }
}

// coords passthrough (tuple element #2)
__global__ void copy_kernel(const float* __restrict__ src, float* __restrict__ dst, int n) {
    int i = blockIdx.x * blockDim.x + threadIdx.x;
    if (i < n) dst[i] = src[i];
}

extern "C" void kernel_launch(void* const* d_in, const int* in_sizes, int n_in,
                              void* d_out, int out_size) {
    const float* coords = (const float*)d_in[0];  // (4096, 6)
    const float* B      = (const float*)d_in[1];  // (3, 128)
    const float* w0     = (const float*)d_in[2];  // (256, 256)
    const float* ws     = (const float*)d_in[3];  // (3, 256, 256)
    const float* w_last = (const float*)d_in[4];  // (256, 256)
    const float* w1     = (const float*)d_in[5];  // (4, 256, 256)
    const float* b1     = (const float*)d_in[6];  // (4, 256)
    float* out = (float*)d_out;

    __nv_bfloat16 *XA, *XB, *Wexp, *Ap, *Bp;
    cudaGetSymbolAddress((void**)&XA, g_XA);
    cudaGetSymbolAddress((void**)&XB, g_XB);
    cudaGetSymbolAddress((void**)&Wexp, g_Wexp);
    cudaGetSymbolAddress((void**)&Ap, g_Ap);
    cudaGetSymbolAddress((void**)&Bp, g_Bp);

    cudaFuncSetAttribute(gemm_kernel<K1, 1>, cudaFuncAttributeMaxDynamicSharedMemorySize, SMEM_TOTAL);
    cudaFuncSetAttribute(gemm_kernel<K1, 2>, cudaFuncAttributeMaxDynamicSharedMemorySize, SMEM_TOTAL);
    cudaFuncSetAttribute(gemm_kernel<KW, 6>, cudaFuncAttributeMaxDynamicSharedMemorySize, SMEM_TOTAL);

    // ---- fork a side stream for the weight-prep chain (graph branch) ----
    cudaStream_t side = nullptr;
    cudaEvent_t evFork = nullptr, evJoin = nullptr;
    bool fork_ok =
        (cudaStreamCreateWithFlags(&side, cudaStreamNonBlocking) == cudaSuccess) &&
        (cudaEventCreateWithFlags(&evFork, cudaEventDisableTiming) == cudaSuccess) &&
        (cudaEventCreateWithFlags(&evJoin, cudaEventDisableTiming) == cudaSuccess);
    if (fork_ok) fork_ok = (cudaEventRecord(evFork, 0) == cudaSuccess) &&
                           (cudaStreamWaitEvent(side, evFork, 0) == cudaSuccess);
    cudaStream_t prepS = fork_ok ? side : (cudaStream_t)0;

    // ---- weight prep chain (side stream when forked) ----
    prep_w_kernel<<<dim3(256, 5), 256, 0, prepS>>>(w1, w_last, Ap, Wexp + (size_t)4 * HID * K1);
    prep_wsinT_kernel<<<dim3(8, 8, 4), dim3(32, 8), 0, prepS>>>(w0, ws, Bp);
    // Single merged prep GEMM: N=512 concat (cols 0-255 -> C1 split, 256-511 -> -C3)
    gemm_kernel<KW, 6><<<dim3(4, 4, 4), 256, SMEM_TOTAL, prepS>>>(
        Ap, Bp, nullptr, Wexp, (size_t)HID * KW, (size_t)512 * KW);

    // ---- activation chain (main stream, concurrent with prep) ----
    fourier_kernel<<<MROWS, 128>>>(coords, B, XA);
    copy_kernel<<<(NCOORD + 255) / 256, 256>>>(coords, out + (size_t)MROWS * HID, NCOORD);

    // ---- join ----
    if (fork_ok) {
        cudaEventRecord(evJoin, side);
        cudaStreamWaitEvent(0, evJoin, 0);
    }

    // ---- network: PDL-chained layer GEMMs ----
    const dim3 grid(MROWS / TILE_M, HID / TILE_N, 1);  // (128, 2) = 256 CTAs
    __nv_bfloat16* bufs[2] = { XA, XB };

    cudaLaunchAttribute pdlAttr[1];
    pdlAttr[0].id = cudaLaunchAttributeProgrammaticStreamSerialization;
    pdlAttr[0].val.programmaticStreamSerializationAllowed = 1;

    for (int l = 0; l < 4; l++) {
        const __nv_bfloat16* Aop = bufs[l & 1];
        const __nv_bfloat16* Bop = Wexp + (size_t)l * HID * K1;
        const float* bop = b1 + l * 256;
        void* Oop = bufs[(l + 1) & 1];
        cudaLaunchConfig_t cfg = {};
        cfg.gridDim = grid; cfg.blockDim = dim3(256, 1, 1);
        cfg.dynamicSmemBytes = SMEM_TOTAL; cfg.stream = 0;
        cfg.attrs = pdlAttr; cfg.numAttrs = 1;
        if (cudaLaunchKernelEx(&cfg, gemm_kernel<K1, 1>, Aop, Bop, bop, Oop,
                               (size_t)0, (size_t)0) != cudaSuccess) {
            gemm_kernel<K1, 1><<<grid, 256, SMEM_TOTAL>>>(Aop, Bop, bop, Oop, 0, 0);
        }
    }
    {
        const __nv_bfloat16* Aop = XA;
        const __nv_bfloat16* Bop = Wexp + (size_t)4 * HID * K1;
        cudaLaunchConfig_t cfg = {};
        cfg.gridDim = grid; cfg.blockDim = dim3(256, 1, 1);
        cfg.dynamicSmemBytes = SMEM_TOTAL; cfg.stream = 0;
        cfg.attrs = pdlAttr; cfg.numAttrs = 1;
        if (cudaLaunchKernelEx(&cfg, gemm_kernel<K1, 2>, Aop, Bop, (const float*)nullptr,
                               (void*)out, (size_t)0, (size_t)0) != cudaSuccess) {
            gemm_kernel<K1, 2><<<grid, 256, SMEM_TOTAL>>>(Aop, Bop, nullptr, out, 0, 0);
        }
    }
    // (stream/event objects intentionally not destroyed: host-side only, few calls)
}